// round 16
// baseline (speedup 1.0000x reference)
#include <cuda_runtime.h>
#include <math_constants.h>
#include <cstdint>

constexpr int BS  = 128;
constexpr int SEQ = 4096;
constexpr int HID = 128;

constexpr int WARPS   = 32;
constexpr int THREADS = WARPS * 32;            // 1024
constexpr int TROWS   = 128;                   // rows per tile
constexpr int TPB     = SEQ / TROWS;           // 32 tiles per batch
constexpr int TILES_TOTAL = BS * TPB;          // 4096
constexpr int STAGES  = 3;
constexpr int TILE_F  = TROWS * HID;           // 16384 floats = 64 KB
constexpr int TILE_B  = TILE_F * 4;            // 65536 bytes
constexpr int MAXC    = 4;                     // max contributors per batch
constexpr int MAX_TILES = 28;                  // ceil(4096/147)
constexpr int SC_ROWS = MAX_TILES * TROWS;     // 3584 score rows in smem

// smem: ring(49152f) + scores(3584f) + acc(4096f) + m/l(64f) + mbar(8f)
constexpr int SMEM_FLOATS = STAGES * TILE_F + SC_ROWS + WARPS * HID + 2 * WARPS + 8;
constexpr size_t SMEM_BYTES = (size_t)SMEM_FLOATS * 4;   // 227,616 B

// Split-softmax scratch + per-batch handshake (zero-init, reset in-kernel)
__device__ float    g_pm[BS * MAXC];
__device__ float    g_pl[BS * MAXC];
__device__ float    g_pacc[BS * MAXC * HID];
__device__ unsigned g_cnt[BS];
__device__ unsigned g_done[BS];

__device__ __forceinline__ uint32_t smem_u32(const void* p) {
    return (uint32_t)__cvta_generic_to_shared(p);
}
__device__ __forceinline__ void mbar_init(uint32_t mbar, uint32_t cnt) {
    asm volatile("mbarrier.init.shared.b64 [%0], %1;" :: "r"(mbar), "r"(cnt) : "memory");
}
__device__ __forceinline__ void mbar_expect_tx(uint32_t mbar, uint32_t bytes) {
    asm volatile("mbarrier.arrive.expect_tx.shared.b64 _, [%0], %1;"
                 :: "r"(mbar), "r"(bytes) : "memory");
}
__device__ __forceinline__ void mbar_wait(uint32_t mbar, uint32_t phase) {
    asm volatile(
        "{\n\t"
        ".reg .pred P1;\n\t"
        "WAIT_%=:\n\t"
        "mbarrier.try_wait.parity.shared::cta.b64 P1, [%0], %1, 0x989680;\n\t"
        "@P1 bra.uni DONE_%=;\n\t"
        "bra.uni WAIT_%=;\n\t"
        "DONE_%=:\n\t"
        "}"
        :: "r"(mbar), "r"(phase) : "memory");
}
__device__ __forceinline__ void tma_bulk_1d(uint32_t smem_dst, const void* gsrc,
                                            uint32_t bytes, uint32_t mbar) {
    asm volatile(
        "cp.async.bulk.shared::cta.global.mbarrier::complete_tx::bytes "
        "[%0], [%1], %2, [%3];"
        :: "r"(smem_dst), "l"(gsrc), "r"(bytes), "r"(mbar) : "memory");
}

// Persistent TMA kernel: grid = #SMs, CTA owns a contiguous balanced run of
// 128-row tiles (tiles never span batches). TMA ring streams uninterrupted;
// softmax state flushes to L2 scratch at the (<=1) batch boundary; per-batch
// counter handshake combines <=3 contributors; probs written from smem.
__global__ __launch_bounds__(THREADS, 1)
void attn_tma_persist(const float* __restrict__ dec,
                      const float* __restrict__ enc,   // [BS*SEQ, HID]
                      float* __restrict__ attn,        // [BS*SEQ] flat
                      float* __restrict__ ctx)         // [BS, HID]
{
    extern __shared__ float smem[];
    float* s_buf    = smem;
    float* s_scores = s_buf + STAGES * TILE_F;
    float* s_acc    = s_scores + SC_ROWS;             // [WARPS][HID]
    float* s_m      = s_acc + WARPS * HID;
    float* s_l      = s_m + WARPS;
    uint64_t* mbar64 = reinterpret_cast<uint64_t*>(s_l + WARPS);
    const uint32_t mb0 = smem_u32(mbar64);

    const int G    = gridDim.x;
    const int bid  = blockIdx.x;
    const int tid  = threadIdx.x;
    const int w    = tid >> 5;
    const int lane = tid & 31;
    const int sub  = lane >> 4;
    const int i    = lane & 15;

    const int ts = (int)((long long)bid * TILES_TOTAL / G);
    const int te = (int)((long long)(bid + 1) * TILES_TOTAL / G);
    const int startRow = ts * TROWS;

    if (tid == 0) {
        #pragma unroll
        for (int s = 0; s < STAGES; ++s) mbar_init(mb0 + 8 * s, 1);
    }
    __syncthreads();

    // prologue: issue first STAGES-1 tiles
    if (tid == 0) {
        #pragma unroll
        for (int k = 0; k < STAGES - 1; ++k) {
            if (ts + k < te) {
                mbar_expect_tx(mb0 + 8 * k, TILE_B);
                tma_bulk_1d(smem_u32(s_buf + k * TILE_F),
                            enc + (size_t)(ts + k) * TILE_F, TILE_B, mb0 + 8 * k);
            }
        }
    }

    float m = 0.f, l = 0.f;
    float4 d0 = make_float4(0,0,0,0), d1 = make_float4(0,0,0,0);
    float4 acc0 = make_float4(0,0,0,0), acc1 = make_float4(0,0,0,0);

    // segment bookkeeping (<=2 segments)
    int sb0v = -1, sr0s = 0, sr0e = 0, sc0v = 0, sn0v = 0;
    int sb1v = -1, sr1s = 0, sr1e = 0, sc1v = 0, sn1v = 0;
    int nseg = 0;
    int curb = -1, segStartRow = 0;

    // flush current segment's partial into L2 scratch + handshake
    auto flush = [&](int endRow) {
        const int b = curb;
        const int first = (int)(((long long)(b * TPB) * G + G - 1) / TILES_TOTAL);
        const int last  = (int)(((long long)(b * TPB + TPB - 1) * G + G - 1) / TILES_TOTAL);
        const int n = last - first + 1;
        const int c = bid - first;

        if (nseg == 0) { sb0v = b; sr0s = segStartRow; sr0e = endRow; sc0v = c; sn0v = n; }
        else           { sb1v = b; sr1s = segStartRow; sr1e = endRow; sc1v = c; sn1v = n; }
        ++nseg;

        // cross-sub combine (segment always has >=1 tile -> m finite)
        float m_o = __shfl_xor_sync(0xFFFFFFFFu, m, 16);
        float l_o = __shfl_xor_sync(0xFFFFFFFFu, l, 16);
        float Mw = fmaxf(m, m_o);
        float sSelf  = __expf(m - Mw);
        float sOther = __expf(m_o - Mw);
        float Lw = l * sSelf + l_o * sOther;

        float t2;
        t2 = __shfl_xor_sync(0xFFFFFFFFu, acc0.x, 16); acc0.x = acc0.x * sSelf + t2 * sOther;
        t2 = __shfl_xor_sync(0xFFFFFFFFu, acc0.y, 16); acc0.y = acc0.y * sSelf + t2 * sOther;
        t2 = __shfl_xor_sync(0xFFFFFFFFu, acc0.z, 16); acc0.z = acc0.z * sSelf + t2 * sOther;
        t2 = __shfl_xor_sync(0xFFFFFFFFu, acc0.w, 16); acc0.w = acc0.w * sSelf + t2 * sOther;
        t2 = __shfl_xor_sync(0xFFFFFFFFu, acc1.x, 16); acc1.x = acc1.x * sSelf + t2 * sOther;
        t2 = __shfl_xor_sync(0xFFFFFFFFu, acc1.y, 16); acc1.y = acc1.y * sSelf + t2 * sOther;
        t2 = __shfl_xor_sync(0xFFFFFFFFu, acc1.z, 16); acc1.z = acc1.z * sSelf + t2 * sOther;
        t2 = __shfl_xor_sync(0xFFFFFFFFu, acc1.w, 16); acc1.w = acc1.w * sSelf + t2 * sOther;

        if (sub == 0) {
            *reinterpret_cast<float4*>(&s_acc[w * HID + i * 4])      = acc0;
            *reinterpret_cast<float4*>(&s_acc[w * HID + 64 + i * 4]) = acc1;
        }
        if (lane == 0) { s_m[w] = Mw; s_l[w] = Lw; }
        __syncthreads();

        float M = -CUDART_INF_F;
        #pragma unroll
        for (int j = 0; j < WARPS; ++j) M = fmaxf(M, s_m[j]);
        float L = 0.f;
        #pragma unroll
        for (int j = 0; j < WARPS; ++j) L += s_l[j] * __expf(s_m[j] - M);

        const int slot = b * MAXC + c;
        if (tid == 0) { g_pm[slot] = M; g_pl[slot] = L; }
        if (tid < HID) {
            float cc = 0.f;
            #pragma unroll
            for (int j = 0; j < WARPS; ++j) cc += s_acc[j * HID + tid] * __expf(s_m[j] - M);
            g_pacc[(size_t)slot * HID + tid] = cc;
        }
        __syncthreads();
        if (tid == 0) {
            __threadfence();
            atomicAdd(&g_cnt[b], 1u);
        }
    };

    int stg = 0, ph = 0;
    int isg = (STAGES - 1) % STAGES;

    for (int t = ts; t < te; ++t) {
        const int tb = t / TPB;
        if (tb != curb) {
            if (curb >= 0) flush(t * TROWS);
            curb = tb; segStartRow = t * TROWS;
            const float* dec_b = dec + (size_t)curb * HID;
            d0 = *reinterpret_cast<const float4*>(dec_b + i * 4);
            d1 = *reinterpret_cast<const float4*>(dec_b + 64 + i * 4);
            m = -CUDART_INF_F; l = 0.f;
            acc0 = make_float4(0,0,0,0); acc1 = make_float4(0,0,0,0);
        }

        if (tid == 0 && t + STAGES - 1 < te) {
            mbar_expect_tx(mb0 + 8 * isg, TILE_B);
            tma_bulk_1d(smem_u32(s_buf + isg * TILE_F),
                        enc + (size_t)(t + STAGES - 1) * TILE_F, TILE_B, mb0 + 8 * isg);
        }
        if (++isg == STAGES) isg = 0;

        mbar_wait(mb0 + 8 * stg, (uint32_t)ph);

        const float* tp = s_buf + stg * TILE_F + (4 * w) * HID;
        const float4 eA0 = *reinterpret_cast<const float4*>(tp + sub * HID + i * 4);
        const float4 eB0 = *reinterpret_cast<const float4*>(tp + sub * HID + 64 + i * 4);
        const float4 eA1 = *reinterpret_cast<const float4*>(tp + (2 + sub) * HID + i * 4);
        const float4 eB1 = *reinterpret_cast<const float4*>(tp + (2 + sub) * HID + 64 + i * 4);

        float scA = eA0.x * d0.x + eA0.y * d0.y + eA0.z * d0.z + eA0.w * d0.w
                  + eB0.x * d1.x + eB0.y * d1.y + eB0.z * d1.z + eB0.w * d1.w;
        float scB = eA1.x * d0.x + eA1.y * d0.y + eA1.z * d0.z + eA1.w * d0.w
                  + eB1.x * d1.x + eB1.y * d1.y + eB1.z * d1.z + eB1.w * d1.w;

        #pragma unroll
        for (int off = 8; off >= 1; off >>= 1) {
            scA += __shfl_xor_sync(0xFFFFFFFFu, scA, off);
            scB += __shfl_xor_sync(0xFFFFFFFFu, scB, off);
        }

        const int rbase = t * TROWS + 4 * w - startRow;
        if (i == 0) {
            s_scores[rbase + sub]     = scA;
            s_scores[rbase + 2 + sub] = scB;
        }

        if (scA > m) {
            float cs = __expf(m - scA);
            m = scA; l *= cs;
            acc0.x *= cs; acc0.y *= cs; acc0.z *= cs; acc0.w *= cs;
            acc1.x *= cs; acc1.y *= cs; acc1.z *= cs; acc1.w *= cs;
        }
        float pA = __expf(scA - m);
        l += pA;
        acc0.x += pA * eA0.x; acc0.y += pA * eA0.y;
        acc0.z += pA * eA0.z; acc0.w += pA * eA0.w;
        acc1.x += pA * eB0.x; acc1.y += pA * eB0.y;
        acc1.z += pA * eB0.z; acc1.w += pA * eB0.w;

        if (scB > m) {
            float cs = __expf(m - scB);
            m = scB; l *= cs;
            acc0.x *= cs; acc0.y *= cs; acc0.z *= cs; acc0.w *= cs;
            acc1.x *= cs; acc1.y *= cs; acc1.z *= cs; acc1.w *= cs;
        }
        float pB = __expf(scB - m);
        l += pB;
        acc0.x += pB * eA1.x; acc0.y += pB * eA1.y;
        acc0.z += pB * eA1.z; acc0.w += pB * eA1.w;
        acc1.x += pB * eB1.x; acc1.y += pB * eB1.y;
        acc1.z += pB * eB1.z; acc1.w += pB * eB1.w;

        __syncthreads();                            // stage recyclable
        if (++stg == STAGES) { stg = 0; ph ^= 1; }
    }
    flush(te * TROWS);

    // ---------------- Phase 2: combine + write own rows ----------------
    #pragma unroll
    for (int k = 0; k < 2; ++k) {
        if (k >= nseg) break;
        const int b  = k ? sb1v : sb0v;
        const int rs = k ? sr1s : sr0s;
        const int re = k ? sr1e : sr0e;
        const int c  = k ? sc1v : sc0v;
        const int n  = k ? sn1v : sn0v;

        if (tid == 0) {
            while (atomicAdd(&g_cnt[b], 0u) < (unsigned)n) __nanosleep(32);
        }
        __syncthreads();

        float pm[MAXC], pl[MAXC];
        for (int j = 0; j < n; ++j) {
            pm[j] = __ldcg(&g_pm[b * MAXC + j]);
            pl[j] = __ldcg(&g_pl[b * MAXC + j]);
        }
        float M = pm[0];
        for (int j = 1; j < n; ++j) M = fmaxf(M, pm[j]);
        float L = 0.f;
        for (int j = 0; j < n; ++j) L += pl[j] * __expf(pm[j] - M);
        const float invL = 1.0f / L;

        if (c == 0 && tid < HID) {
            float cc = 0.f;
            for (int j = 0; j < n; ++j)
                cc += __ldcg(&g_pacc[(size_t)(b * MAXC + j) * HID + tid])
                      * __expf(pm[j] - M);
            ctx[(size_t)b * HID + tid] = cc * invL;
        }

        // rows per segment are multiples of TROWS=128 -> float4 clean
        for (int idx = rs + tid * 4; idx < re; idx += THREADS * 4) {
            float4 v = *reinterpret_cast<const float4*>(&s_scores[idx - startRow]);
            v.x = __expf(v.x - M) * invL;
            v.y = __expf(v.y - M) * invL;
            v.z = __expf(v.z - M) * invL;
            v.w = __expf(v.w - M) * invL;
            *reinterpret_cast<float4*>(attn + idx) = v;
        }
        __syncthreads();
        if (tid == 0) atomicAdd(&g_done[b], 1u);
    }

    // reset per-batch counters for next graph replay
    if (tid == 0) {
        if (nseg >= 1 && sc0v == 0) {
            while (atomicAdd(&g_done[sb0v], 0u) < (unsigned)sn0v) __nanosleep(32);
            atomicExch(&g_cnt[sb0v], 0u);
            atomicExch(&g_done[sb0v], 0u);
        }
        if (nseg >= 2 && sc1v == 0) {
            while (atomicAdd(&g_done[sb1v], 0u) < (unsigned)sn1v) __nanosleep(32);
            atomicExch(&g_cnt[sb1v], 0u);
            atomicExch(&g_done[sb1v], 0u);
        }
    }
}

extern "C" void kernel_launch(void* const* d_in, const int* in_sizes, int n_in,
                              void* d_out, int out_size)
{
    const float* dec = (const float*)d_in[0];
    const float* enc = (const float*)d_in[1];
    if (n_in >= 2 && in_sizes[0] > in_sizes[1]) {
        dec = (const float*)d_in[1];
        enc = (const float*)d_in[0];
    }

    float* attn = (float*)d_out;                   // [BS*SEQ] flat
    float* ctx  = attn + (size_t)BS * SEQ;         // [BS, HID]

    int dev = 0, sms = 148;
    cudaGetDevice(&dev);
    cudaDeviceGetAttribute(&sms, cudaDevAttrMultiProcessorCount, dev);
    if (sms < 147) sms = 147;                      // SC_ROWS coverage guard
    if (sms > 512) sms = 512;

    cudaFuncSetAttribute(attn_tma_persist,
                         cudaFuncAttributeMaxDynamicSharedMemorySize,
                         (int)SMEM_BYTES);

    attn_tma_persist<<<sms, THREADS, SMEM_BYTES>>>(dec, enc, attn, ctx);
}